// round 11
// baseline (speedup 1.0000x reference)
#include <cuda_runtime.h>

#define NN 100000
#define EE 1600000
#define BB 512
#define HH 4
#define DD 64
#define HD 256
#define EXTRA 16
#define YW (HD + EXTRA)   // 272

// ---------------- scratch (no allocations allowed) ----------------
__device__ __align__(16) float g_h[(size_t)NN * HD];   // GEMM output h
__device__ __align__(16) float g_x[(size_t)NN * HD];   // layer activations
__device__ __align__(16) float g_el[NN * HH];
__device__ __align__(16) float g_er[NN * HH];
__device__ int   g_deg[NN];
__device__ int   g_rowstart[NN + 1];
__device__ int   g_cursor[NN];
__device__ int   g_col[EE];          // src node per CSR slot (grouped by dst)
__device__ float g_w[NN];            // readout scores
__device__ int   g_gstart[BB + 1];
__device__ __align__(16) float g_y[BB * YW];

__device__ __forceinline__ float seluf(float v) {
    const float a = 1.6732632423543772f, s = 1.0507009873554805f;
    return v > 0.f ? s * v : s * a * (expf(v) - 1.f);
}
__device__ __forceinline__ float lrelu(float v) { return v > 0.f ? v : 0.2f * v; }

// ---------------- CSR build ----------------
__global__ void zero_deg_kernel() {
    int i = blockIdx.x * blockDim.x + threadIdx.x;
    if (i < NN) g_deg[i] = 0;
}
__global__ void hist_kernel(const int* __restrict__ dst) {
    int e = blockIdx.x * blockDim.x + threadIdx.x;
    if (e < EE) atomicAdd(&g_deg[dst[e]], 1);
}
__global__ __launch_bounds__(1024) void scan_kernel() {
    __shared__ int sm[1024];
    __shared__ int carry;
    if (threadIdx.x == 0) { carry = 0; g_rowstart[0] = 0; }
    __syncthreads();
    for (int base = 0; base < NN; base += 1024) {
        int i = base + threadIdx.x;
        int v = (i < NN) ? g_deg[i] : 0;
        sm[threadIdx.x] = v;
        __syncthreads();
        for (int off = 1; off < 1024; off <<= 1) {
            int t = (threadIdx.x >= off) ? sm[threadIdx.x - off] : 0;
            __syncthreads();
            sm[threadIdx.x] += t;
            __syncthreads();
        }
        if (i < NN) {
            int inc = carry + sm[threadIdx.x];
            g_rowstart[i + 1] = inc;
            g_cursor[i] = inc - v;   // exclusive prefix
        }
        __syncthreads();
        if (threadIdx.x == 1023) carry += sm[1023];
        __syncthreads();
    }
}
__global__ void scatter_kernel(const int* __restrict__ src, const int* __restrict__ dst) {
    int e = blockIdx.x * blockDim.x + threadIdx.x;
    if (e < EE) {
        int pos = atomicAdd(&g_cursor[dst[e]], 1);
        g_col[pos] = src[e];
    }
}

// ---------------- GEMM: C[M,256] = A[M,K] @ B[K,256]  (C = g_h) ----------------
__global__ __launch_bounds__(256) void gemm_kernel(const float* __restrict__ A_ext,
                                                   int use_gx,
                                                   const float* __restrict__ B,
                                                   int Kdim) {
    const float* __restrict__ A = use_gx ? g_x : A_ext;
    __shared__ float As[8][128];
    __shared__ float Bs[8][128];
    int tid = threadIdx.x;
    int bm = blockIdx.y * 128;
    int bn = blockIdx.x * 128;
    int a_row = tid >> 1;            // 0..127
    int a_k   = (tid & 1) << 2;      // 0 or 4
    int b_k   = tid >> 5;            // 0..7
    int b_n   = (tid & 31) << 2;     // 0..124
    int ty = tid >> 4, tx = tid & 15;

    float acc[8][8];
#pragma unroll
    for (int i = 0; i < 8; i++)
#pragma unroll
        for (int j = 0; j < 8; j++) acc[i][j] = 0.f;

    for (int k0 = 0; k0 < Kdim; k0 += 8) {
        float4 av = make_float4(0.f, 0.f, 0.f, 0.f);
        int gr = bm + a_row;
        if (gr < NN) av = *(const float4*)(A + (size_t)gr * Kdim + k0 + a_k);
        As[a_k + 0][a_row] = av.x;
        As[a_k + 1][a_row] = av.y;
        As[a_k + 2][a_row] = av.z;
        As[a_k + 3][a_row] = av.w;
        float4 bv = *(const float4*)(B + (size_t)(k0 + b_k) * 256 + bn + b_n);
        *(float4*)&Bs[b_k][b_n] = bv;
        __syncthreads();
#pragma unroll
        for (int k = 0; k < 8; k++) {
            float ar_[8], br_[8];
#pragma unroll
            for (int i = 0; i < 8; i++) ar_[i] = As[k][ty * 8 + i];
#pragma unroll
            for (int j = 0; j < 8; j++) br_[j] = Bs[k][tx * 8 + j];
#pragma unroll
            for (int i = 0; i < 8; i++)
#pragma unroll
                for (int j = 0; j < 8; j++) acc[i][j] += ar_[i] * br_[j];
        }
        __syncthreads();
    }
#pragma unroll
    for (int i = 0; i < 8; i++) {
        int gr = bm + ty * 8 + i;
        if (gr < NN) {
            float* cp = g_h + (size_t)gr * 256 + bn + tx * 8;
            *(float4*)cp       = make_float4(acc[i][0], acc[i][1], acc[i][2], acc[i][3]);
            *(float4*)(cp + 4) = make_float4(acc[i][4], acc[i][5], acc[i][6], acc[i][7]);
        }
    }
}

// ---------------- per-node attention logits el/er ----------------
__global__ __launch_bounds__(256) void elr_kernel(const float* __restrict__ al,
                                                  const float* __restrict__ ar) {
    int lane = threadIdx.x & 31;
    int v = blockIdx.x * 8 + (threadIdx.x >> 5);
    if (v >= NN) return;
    const float* hrow = g_h + (size_t)v * HD;
    float pl[4] = {0.f, 0.f, 0.f, 0.f}, pr[4] = {0.f, 0.f, 0.f, 0.f};
#pragma unroll
    for (int k = 0; k < 8; k++) {
        int dim = lane + 32 * k;
        float hv = hrow[dim];
        pl[k >> 1] += hv * al[dim];
        pr[k >> 1] += hv * ar[dim];
    }
#pragma unroll
    for (int off = 16; off; off >>= 1) {
#pragma unroll
        for (int h = 0; h < 4; h++) {
            pl[h] += __shfl_xor_sync(0xffffffffu, pl[h], off);
            pr[h] += __shfl_xor_sync(0xffffffffu, pr[h], off);
        }
    }
    if (lane == 0) {
        ((float4*)g_el)[v] = make_float4(pl[0], pl[1], pl[2], pl[3]);
        ((float4*)g_er)[v] = make_float4(pr[0], pr[1], pr[2], pr[3]);
    }
}

// ---------------- segment-softmax + weighted aggregate (one warp per dst node) ----------------
__global__ __launch_bounds__(256) void aggregate_kernel(const float* __restrict__ bias) {
    __shared__ int    s_src[8][32];
    __shared__ float4 s_w[8][32];
    int lane = threadIdx.x & 31;
    int wslot = threadIdx.x >> 5;
    int v = blockIdx.x * 8 + wslot;
    if (v >= NN) return;
    int start = g_rowstart[v], end = g_rowstart[v + 1];
    float4 erv = ((const float4*)g_er)[v];

    // pass 1: per-head max
    float m0 = -1e30f, m1 = -1e30f, m2 = -1e30f, m3 = -1e30f;
    for (int i = start + lane; i < end; i += 32) {
        int s = g_col[i];
        float4 elv = ((const float4*)g_el)[s];
        m0 = fmaxf(m0, lrelu(elv.x + erv.x));
        m1 = fmaxf(m1, lrelu(elv.y + erv.y));
        m2 = fmaxf(m2, lrelu(elv.z + erv.z));
        m3 = fmaxf(m3, lrelu(elv.w + erv.w));
    }
#pragma unroll
    for (int off = 16; off; off >>= 1) {
        m0 = fmaxf(m0, __shfl_xor_sync(0xffffffffu, m0, off));
        m1 = fmaxf(m1, __shfl_xor_sync(0xffffffffu, m1, off));
        m2 = fmaxf(m2, __shfl_xor_sync(0xffffffffu, m2, off));
        m3 = fmaxf(m3, __shfl_xor_sync(0xffffffffu, m3, off));
    }

    // pass 2: exp weights + weighted gather of h[src]
    float acc[8];
#pragma unroll
    for (int k = 0; k < 8; k++) acc[k] = 0.f;
    float den0 = 0.f, den1 = 0.f, den2 = 0.f, den3 = 0.f;

    for (int base = start; base < end; base += 32) {
        int idx = base + lane;
        if (idx < end) {
            int s = g_col[idx];
            float4 elv = ((const float4*)g_el)[s];
            float4 wv;
            wv.x = expf(lrelu(elv.x + erv.x) - m0);
            wv.y = expf(lrelu(elv.y + erv.y) - m1);
            wv.z = expf(lrelu(elv.z + erv.z) - m2);
            wv.w = expf(lrelu(elv.w + erv.w) - m3);
            s_src[wslot][lane] = s;
            s_w[wslot][lane] = wv;
        }
        __syncwarp();
        int cnt = min(32, end - base);
        for (int j = 0; j < cnt; j++) {
            int s = s_src[wslot][j];
            float4 wv = s_w[wslot][j];
            den0 += wv.x; den1 += wv.y; den2 += wv.z; den3 += wv.w;
            const float* hrow = g_h + (size_t)s * HD;
            float warr[4] = {wv.x, wv.y, wv.z, wv.w};
#pragma unroll
            for (int k = 0; k < 8; k++)
                acc[k] += warr[k >> 1] * hrow[lane + 32 * k];
        }
        __syncwarp();
    }
    float den[4] = {den0, den1, den2, den3};
    float* xrow = g_x + (size_t)v * HD;
#pragma unroll
    for (int k = 0; k < 8; k++) {
        int dim = lane + 32 * k;
        float val = acc[k] / fmaxf(den[k >> 1], 1e-9f) + bias[dim];
        xrow[dim] = seluf(val);
    }
}

// ---------------- readout ----------------
__global__ __launch_bounds__(256) void score_kernel(const float* __restrict__ sw,
                                                    const float* __restrict__ sb) {
    int lane = threadIdx.x & 31;
    int v = blockIdx.x * 8 + (threadIdx.x >> 5);
    if (v >= NN) return;
    const float* xr = g_x + (size_t)v * HD;
    float p = 0.f;
#pragma unroll
    for (int k = 0; k < 8; k++) { int dim = lane + 32 * k; p += xr[dim] * sw[dim]; }
#pragma unroll
    for (int off = 16; off; off >>= 1) p += __shfl_xor_sync(0xffffffffu, p, off);
    if (lane == 0) g_w[v] = 1.f / (1.f + expf(-(p + sb[0])));
}

__global__ void boundary_kernel(const int* __restrict__ ng) {
    int i = blockIdx.x * blockDim.x + threadIdx.x;
    if (i >= NN) return;
    int g = ng[i];
    int pg = (i == 0) ? -1 : ng[i - 1];
    for (int gg = pg + 1; gg <= g; gg++) g_gstart[gg] = i;
    if (i == NN - 1)
        for (int gg = g + 1; gg <= BB; gg++) g_gstart[gg] = NN;
}

__global__ __launch_bounds__(256) void readout_kernel(const float* __restrict__ fg) {
    int g = blockIdx.x, d = threadIdx.x;
    int s = g_gstart[g], e = g_gstart[g + 1];
    float num = 0.f, ws = 0.f;
    for (int i = s; i < e; i++) {
        float wv = g_w[i];
        num += wv * g_x[(size_t)i * HD + d];
        ws += wv;
    }
    g_y[g * YW + d] = num / fmaxf(ws, 1e-9f);
    if (d < EXTRA) g_y[g * YW + HD + d] = fg[g * EXTRA + d];
}

// ---------------- MLP head ----------------
__global__ __launch_bounds__(128) void mlp_kernel(const float* __restrict__ lw1,
                                                  const float* __restrict__ lb1,
                                                  const float* __restrict__ lw2,
                                                  const float* __restrict__ lb2,
                                                  const float* __restrict__ lw3,
                                                  const float* __restrict__ lb3,
                                                  float* __restrict__ out) {
    __shared__ float yrow[YW];
    __shared__ float h1[128];
    __shared__ float h2[64];
    int g = blockIdx.x, t = threadIdx.x;
    const float* y = g_y + g * YW;
    yrow[t] = y[t];
    yrow[t + 128] = y[t + 128];
    if (t < 16) yrow[t + 256] = y[t + 256];
    __syncthreads();
    float s = lb1[t];
#pragma unroll 8
    for (int j = 0; j < YW; j++) s += yrow[j] * lw1[j * 128 + t];
    h1[t] = seluf(s);
    __syncthreads();
    if (t < 64) {
        float s2 = lb2[t];
#pragma unroll 8
        for (int j = 0; j < 128; j++) s2 += h1[j] * lw2[j * 64 + t];
        h2[t] = seluf(s2);
    }
    __syncthreads();
    if (t < 32) {
        float p = h2[t] * lw3[t] + h2[t + 32] * lw3[t + 32];
#pragma unroll
        for (int off = 16; off; off >>= 1) p += __shfl_xor_sync(0xffffffffu, p, off);
        if (t == 0) out[g] = p + lb3[0];
    }
}

// ---------------- launch ----------------
extern "C" void kernel_launch(void* const* d_in, const int* in_sizes, int n_in,
                              void* d_out, int out_size) {
    const int*   src = (const int*)d_in[0];
    const int*   dst = (const int*)d_in[1];
    const int*   ng  = (const int*)d_in[2];
    const float* feats_node  = (const float*)d_in[3];
    const float* feats_graph = (const float*)d_in[4];
    const float* W1  = (const float*)d_in[5];
    const float* al1 = (const float*)d_in[6];
    const float* ar1 = (const float*)d_in[7];
    const float* bg1 = (const float*)d_in[8];
    const float* W2  = (const float*)d_in[9];
    const float* al2 = (const float*)d_in[10];
    const float* ar2 = (const float*)d_in[11];
    const float* bg2 = (const float*)d_in[12];
    const float* W3  = (const float*)d_in[13];
    const float* al3 = (const float*)d_in[14];
    const float* ar3 = (const float*)d_in[15];
    const float* bg3 = (const float*)d_in[16];
    const float* sw  = (const float*)d_in[17];
    const float* sb  = (const float*)d_in[18];
    const float* lw1 = (const float*)d_in[19];
    const float* lb1 = (const float*)d_in[20];
    const float* lw2 = (const float*)d_in[21];
    const float* lb2 = (const float*)d_in[22];
    const float* lw3 = (const float*)d_in[23];
    const float* lb3 = (const float*)d_in[24];
    float* out = (float*)d_out;

    // CSR by dst (rebuilt every call: no caching allowed)
    zero_deg_kernel<<<(NN + 255) / 256, 256>>>();
    hist_kernel<<<(EE + 255) / 256, 256>>>(dst);
    scan_kernel<<<1, 1024>>>();
    scatter_kernel<<<(EE + 255) / 256, 256>>>(src, dst);

    dim3 ggrid(2, (NN + 127) / 128);
    const int nwb = NN / 8;  // 12500 blocks of 8 warps

    // layer 1
    gemm_kernel<<<ggrid, 256>>>(feats_node, 0, W1, 64);
    elr_kernel<<<nwb, 256>>>(al1, ar1);
    aggregate_kernel<<<nwb, 256>>>(bg1);
    // layer 2
    gemm_kernel<<<ggrid, 256>>>(nullptr, 1, W2, 256);
    elr_kernel<<<nwb, 256>>>(al2, ar2);
    aggregate_kernel<<<nwb, 256>>>(bg2);
    // layer 3
    gemm_kernel<<<ggrid, 256>>>(nullptr, 1, W3, 256);
    elr_kernel<<<nwb, 256>>>(al3, ar3);
    aggregate_kernel<<<nwb, 256>>>(bg3);

    // readout + MLP
    score_kernel<<<nwb, 256>>>(sw, sb);
    boundary_kernel<<<(NN + 255) / 256, 256>>>(ng);
    readout_kernel<<<BB, 256>>>(feats_graph);
    mlp_kernel<<<BB, 128>>>(lw1, lb1, lw2, lb2, lw3, lb3, out);
}

// round 13
// speedup vs baseline: 1.1071x; 1.1071x over previous
#include <cuda_runtime.h>

#define NN 100000
#define EE 1600000
#define BB 512
#define HH 4
#define DD 64
#define HD 256
#define EXTRA 16
#define YW (HD + EXTRA)   // 272
#define KC 16             // GEMM K-chunk

// ---------------- scratch (no allocations allowed) ----------------
__device__ __align__(16) float g_h[(size_t)NN * HD];   // GEMM output h
__device__ __align__(16) float g_x[(size_t)NN * HD];   // layer activations
__device__ __align__(16) float g_el[NN * HH];
__device__ __align__(16) float g_er[NN * HH];
__device__ int   g_deg[NN];
__device__ int   g_rowstart[NN + 1];
__device__ int   g_cursor[NN];
__device__ int   g_col[EE];          // src node per CSR slot (grouped by dst)
__device__ float g_w[NN];            // readout scores
__device__ int   g_gstart[BB + 1];
__device__ __align__(16) float g_y[BB * YW];
__device__ int   g_bsum[128];
__device__ int   g_boff[128];

__device__ __forceinline__ float seluf(float v) {
    const float a = 1.6732632423543772f, s = 1.0507009873554805f;
    return v > 0.f ? s * v : s * a * (expf(v) - 1.f);
}
__device__ __forceinline__ float lrelu(float v) { return v > 0.f ? v : 0.2f * v; }

// packed fp32x2 helpers (Blackwell FFMA2 path — only reachable via PTX)
__device__ __forceinline__ unsigned long long ffma2(unsigned long long a,
                                                    unsigned long long b,
                                                    unsigned long long c) {
    unsigned long long d;
    asm("fma.rn.f32x2 %0, %1, %2, %3;" : "=l"(d) : "l"(a), "l"(b), "l"(c));
    return d;
}
__device__ __forceinline__ unsigned long long pack2(float lo, float hi) {
    unsigned long long v;
    asm("mov.b64 %0, {%1, %2};" : "=l"(v) : "f"(lo), "f"(hi));
    return v;
}
__device__ __forceinline__ void unpack2(unsigned long long v, float& lo, float& hi) {
    asm("mov.b64 {%0, %1}, %2;" : "=f"(lo), "=f"(hi) : "l"(v));
}

// ---------------- CSR build ----------------
__global__ void zero_deg_kernel() {
    int i = blockIdx.x * blockDim.x + threadIdx.x;
    if (i < NN) g_deg[i] = 0;
}
__global__ void hist_kernel(const int* __restrict__ dst) {
    int e = blockIdx.x * blockDim.x + threadIdx.x;
    if (e < EE) atomicAdd(&g_deg[dst[e]], 1);
}
// 3-phase parallel scan of g_deg -> g_rowstart (inclusive at i+1) + g_cursor (exclusive)
__global__ __launch_bounds__(1024) void scan_local_kernel() {
    __shared__ int sm[1024];
    int i = blockIdx.x * 1024 + threadIdx.x;
    int v = (i < NN) ? g_deg[i] : 0;
    sm[threadIdx.x] = v;
    __syncthreads();
    for (int off = 1; off < 1024; off <<= 1) {
        int t = (threadIdx.x >= off) ? sm[threadIdx.x - off] : 0;
        __syncthreads();
        sm[threadIdx.x] += t;
        __syncthreads();
    }
    if (i < NN) g_cursor[i] = sm[threadIdx.x];   // local inclusive
    if (threadIdx.x == 1023) g_bsum[blockIdx.x] = sm[1023];
}
__global__ __launch_bounds__(128) void scan_bsum_kernel(int nblocks) {
    __shared__ int sm[128];
    int v = (threadIdx.x < nblocks) ? g_bsum[threadIdx.x] : 0;
    sm[threadIdx.x] = v;
    __syncthreads();
    for (int off = 1; off < 128; off <<= 1) {
        int t = (threadIdx.x >= off) ? sm[threadIdx.x - off] : 0;
        __syncthreads();
        sm[threadIdx.x] += t;
        __syncthreads();
    }
    g_boff[threadIdx.x] = sm[threadIdx.x] - v;   // exclusive
}
__global__ __launch_bounds__(1024) void scan_finalize_kernel() {
    int i = blockIdx.x * 1024 + threadIdx.x;
    if (i >= NN) return;
    int inc = g_cursor[i] + g_boff[blockIdx.x];
    g_rowstart[i + 1] = inc;
    g_cursor[i] = inc - g_deg[i];
    if (i == 0) g_rowstart[0] = 0;
}
__global__ void scatter_kernel(const int* __restrict__ src, const int* __restrict__ dst) {
    int e = blockIdx.x * blockDim.x + threadIdx.x;
    if (e < EE) {
        int pos = atomicAdd(&g_cursor[dst[e]], 1);
        g_col[pos] = src[e];
    }
}

// ---------------- GEMM: C[M,256] = A[M,K] @ B[K,256]  (C = g_h), packed f32x2 ----------------
__global__ __launch_bounds__(256) void gemm_kernel(const float* __restrict__ A_ext,
                                                   int use_gx,
                                                   const float* __restrict__ B,
                                                   int Kdim) {
    const float* __restrict__ A = use_gx ? g_x : A_ext;
    __shared__ float As[KC][128];
    __shared__ float Bs[KC][128];
    int tid = threadIdx.x;
    int bm = blockIdx.y * 128;
    int bn = blockIdx.x * 128;
    int a_row = tid >> 1;            // 0..127
    int a_k   = (tid & 1) << 3;      // 0 or 8
    int b_k   = tid >> 4;            // 0..15
    int b_n   = (tid & 15) << 3;     // 0..120
    int ty = tid >> 4, tx = tid & 15;

    unsigned long long acc2[8][4];
#pragma unroll
    for (int i = 0; i < 8; i++)
#pragma unroll
        for (int j = 0; j < 4; j++) acc2[i][j] = 0ull;

    int gr_a = bm + a_row;
    bool a_ok = gr_a < NN;
    const float* Arow = A + (size_t)gr_a * Kdim;

    for (int k0 = 0; k0 < Kdim; k0 += KC) {
        float4 av0 = make_float4(0.f, 0.f, 0.f, 0.f), av1 = av0;
        if (a_ok) {
            av0 = *(const float4*)(Arow + k0 + a_k);
            av1 = *(const float4*)(Arow + k0 + a_k + 4);
        }
        As[a_k + 0][a_row] = av0.x; As[a_k + 1][a_row] = av0.y;
        As[a_k + 2][a_row] = av0.z; As[a_k + 3][a_row] = av0.w;
        As[a_k + 4][a_row] = av1.x; As[a_k + 5][a_row] = av1.y;
        As[a_k + 6][a_row] = av1.z; As[a_k + 7][a_row] = av1.w;
        const float* Brow = B + (size_t)(k0 + b_k) * 256 + bn + b_n;
        *(float4*)&Bs[b_k][b_n]     = *(const float4*)(Brow);
        *(float4*)&Bs[b_k][b_n + 4] = *(const float4*)(Brow + 4);
        __syncthreads();
#pragma unroll
        for (int k = 0; k < KC; k++) {
            float a_[8];
            *(float4*)&a_[0] = *(const float4*)&As[k][ty * 8];
            *(float4*)&a_[4] = *(const float4*)&As[k][ty * 8 + 4];
            ulonglong2 blo = *(const ulonglong2*)&Bs[k][tx * 8];
            ulonglong2 bhi = *(const ulonglong2*)&Bs[k][tx * 8 + 4];
            unsigned long long b2[4] = {blo.x, blo.y, bhi.x, bhi.y};
#pragma unroll
            for (int i = 0; i < 8; i++) {
                unsigned long long pa = pack2(a_[i], a_[i]);
#pragma unroll
                for (int j = 0; j < 4; j++) acc2[i][j] = ffma2(pa, b2[j], acc2[i][j]);
            }
        }
        __syncthreads();
    }
#pragma unroll
    for (int i = 0; i < 8; i++) {
        int gr = bm + ty * 8 + i;
        if (gr < NN) {
            float c[8];
#pragma unroll
            for (int j = 0; j < 4; j++) unpack2(acc2[i][j], c[2 * j], c[2 * j + 1]);
            float* cp = g_h + (size_t)gr * 256 + bn + tx * 8;
            *(float4*)cp       = make_float4(c[0], c[1], c[2], c[3]);
            *(float4*)(cp + 4) = make_float4(c[4], c[5], c[6], c[7]);
        }
    }
}

// ---------------- per-node attention logits el/er ----------------
__global__ __launch_bounds__(256) void elr_kernel(const float* __restrict__ al,
                                                  const float* __restrict__ ar) {
    int lane = threadIdx.x & 31;
    int v = blockIdx.x * 8 + (threadIdx.x >> 5);
    if (v >= NN) return;
    const float* hrow = g_h + (size_t)v * HD;
    float pl[4] = {0.f, 0.f, 0.f, 0.f}, pr[4] = {0.f, 0.f, 0.f, 0.f};
#pragma unroll
    for (int k = 0; k < 8; k++) {
        int dim = lane + 32 * k;
        float hv = hrow[dim];
        pl[k >> 1] += hv * al[dim];
        pr[k >> 1] += hv * ar[dim];
    }
#pragma unroll
    for (int off = 16; off; off >>= 1) {
#pragma unroll
        for (int h = 0; h < 4; h++) {
            pl[h] += __shfl_xor_sync(0xffffffffu, pl[h], off);
            pr[h] += __shfl_xor_sync(0xffffffffu, pr[h], off);
        }
    }
    if (lane == 0) {
        ((float4*)g_el)[v] = make_float4(pl[0], pl[1], pl[2], pl[3]);
        ((float4*)g_er)[v] = make_float4(pr[0], pr[1], pr[2], pr[3]);
    }
}

// ---------------- segment-softmax + weighted aggregate (one warp per dst node) ----------------
__global__ __launch_bounds__(256) void aggregate_kernel(const float* __restrict__ bias) {
    __shared__ int    s_src[8][32];
    __shared__ float4 s_w[8][32];
    int lane = threadIdx.x & 31;
    int wslot = threadIdx.x >> 5;
    int v = blockIdx.x * 8 + wslot;
    if (v >= NN) return;
    int start = g_rowstart[v], end = g_rowstart[v + 1];
    float4 erv = ((const float4*)g_er)[v];

    // pass 1: per-head max
    float m0 = -1e30f, m1 = -1e30f, m2 = -1e30f, m3 = -1e30f;
    for (int i = start + lane; i < end; i += 32) {
        int s = g_col[i];
        float4 elv = ((const float4*)g_el)[s];
        m0 = fmaxf(m0, lrelu(elv.x + erv.x));
        m1 = fmaxf(m1, lrelu(elv.y + erv.y));
        m2 = fmaxf(m2, lrelu(elv.z + erv.z));
        m3 = fmaxf(m3, lrelu(elv.w + erv.w));
    }
#pragma unroll
    for (int off = 16; off; off >>= 1) {
        m0 = fmaxf(m0, __shfl_xor_sync(0xffffffffu, m0, off));
        m1 = fmaxf(m1, __shfl_xor_sync(0xffffffffu, m1, off));
        m2 = fmaxf(m2, __shfl_xor_sync(0xffffffffu, m2, off));
        m3 = fmaxf(m3, __shfl_xor_sync(0xffffffffu, m3, off));
    }

    // pass 2: exp weights + weighted gather of h[src]
    float acc[8];
#pragma unroll
    for (int k = 0; k < 8; k++) acc[k] = 0.f;
    float den0 = 0.f, den1 = 0.f, den2 = 0.f, den3 = 0.f;

    for (int base = start; base < end; base += 32) {
        int idx = base + lane;
        if (idx < end) {
            int s = g_col[idx];
            float4 elv = ((const float4*)g_el)[s];
            float4 wv;
            wv.x = expf(lrelu(elv.x + erv.x) - m0);
            wv.y = expf(lrelu(elv.y + erv.y) - m1);
            wv.z = expf(lrelu(elv.z + erv.z) - m2);
            wv.w = expf(lrelu(elv.w + erv.w) - m3);
            s_src[wslot][lane] = s;
            s_w[wslot][lane] = wv;
        }
        __syncwarp();
        int cnt = min(32, end - base);
        for (int j = 0; j < cnt; j++) {
            int s = s_src[wslot][j];
            float4 wv = s_w[wslot][j];
            den0 += wv.x; den1 += wv.y; den2 += wv.z; den3 += wv.w;
            const float* hrow = g_h + (size_t)s * HD;
            float warr[4] = {wv.x, wv.y, wv.z, wv.w};
#pragma unroll
            for (int k = 0; k < 8; k++)
                acc[k] += warr[k >> 1] * hrow[lane + 32 * k];
        }
        __syncwarp();
    }
    float den[4] = {den0, den1, den2, den3};
    float* xrow = g_x + (size_t)v * HD;
#pragma unroll
    for (int k = 0; k < 8; k++) {
        int dim = lane + 32 * k;
        float val = acc[k] / fmaxf(den[k >> 1], 1e-9f) + bias[dim];
        xrow[dim] = seluf(val);
    }
}

// ---------------- readout ----------------
__global__ __launch_bounds__(256) void score_kernel(const float* __restrict__ sw,
                                                    const float* __restrict__ sb) {
    int lane = threadIdx.x & 31;
    int v = blockIdx.x * 8 + (threadIdx.x >> 5);
    if (v >= NN) return;
    const float* xr = g_x + (size_t)v * HD;
    float p = 0.f;
#pragma unroll
    for (int k = 0; k < 8; k++) { int dim = lane + 32 * k; p += xr[dim] * sw[dim]; }
#pragma unroll
    for (int off = 16; off; off >>= 1) p += __shfl_xor_sync(0xffffffffu, p, off);
    if (lane == 0) g_w[v] = 1.f / (1.f + expf(-(p + sb[0])));
}

__global__ void boundary_kernel(const int* __restrict__ ng) {
    int i = blockIdx.x * blockDim.x + threadIdx.x;
    if (i >= NN) return;
    int g = ng[i];
    int pg = (i == 0) ? -1 : ng[i - 1];
    for (int gg = pg + 1; gg <= g; gg++) g_gstart[gg] = i;
    if (i == NN - 1)
        for (int gg = g + 1; gg <= BB; gg++) g_gstart[gg] = NN;
}

__global__ __launch_bounds__(256) void readout_kernel(const float* __restrict__ fg) {
    int g = blockIdx.x, d = threadIdx.x;
    int s = g_gstart[g], e = g_gstart[g + 1];
    float num = 0.f, ws = 0.f;
    for (int i = s; i < e; i++) {
        float wv = g_w[i];
        num += wv * g_x[(size_t)i * HD + d];
        ws += wv;
    }
    g_y[g * YW + d] = num / fmaxf(ws, 1e-9f);
    if (d < EXTRA) g_y[g * YW + HD + d] = fg[g * EXTRA + d];
}

// ---------------- MLP head ----------------
__global__ __launch_bounds__(128) void mlp_kernel(const float* __restrict__ lw1,
                                                  const float* __restrict__ lb1,
                                                  const float* __restrict__ lw2,
                                                  const float* __restrict__ lb2,
                                                  const float* __restrict__ lw3,
                                                  const float* __restrict__ lb3,
                                                  float* __restrict__ out) {
    __shared__ float yrow[YW];
    __shared__ float h1[128];
    __shared__ float h2[64];
    int g = blockIdx.x, t = threadIdx.x;
    const float* y = g_y + g * YW;
    yrow[t] = y[t];
    yrow[t + 128] = y[t + 128];
    if (t < 16) yrow[t + 256] = y[t + 256];
    __syncthreads();
    float s = lb1[t];
#pragma unroll 8
    for (int j = 0; j < YW; j++) s += yrow[j] * lw1[j * 128 + t];
    h1[t] = seluf(s);
    __syncthreads();
    if (t < 64) {
        float s2 = lb2[t];
#pragma unroll 8
        for (int j = 0; j < 128; j++) s2 += h1[j] * lw2[j * 64 + t];
        h2[t] = seluf(s2);
    }
    __syncthreads();
    if (t < 32) {
        float p = h2[t] * lw3[t] + h2[t + 32] * lw3[t + 32];
#pragma unroll
        for (int off = 16; off; off >>= 1) p += __shfl_xor_sync(0xffffffffu, p, off);
        if (t == 0) out[g] = p + lb3[0];
    }
}

// ---------------- launch ----------------
extern "C" void kernel_launch(void* const* d_in, const int* in_sizes, int n_in,
                              void* d_out, int out_size) {
    const int*   src = (const int*)d_in[0];
    const int*   dst = (const int*)d_in[1];
    const int*   ng  = (const int*)d_in[2];
    const float* feats_node  = (const float*)d_in[3];
    const float* feats_graph = (const float*)d_in[4];
    const float* W1  = (const float*)d_in[5];
    const float* al1 = (const float*)d_in[6];
    const float* ar1 = (const float*)d_in[7];
    const float* bg1 = (const float*)d_in[8];
    const float* W2  = (const float*)d_in[9];
    const float* al2 = (const float*)d_in[10];
    const float* ar2 = (const float*)d_in[11];
    const float* bg2 = (const float*)d_in[12];
    const float* W3  = (const float*)d_in[13];
    const float* al3 = (const float*)d_in[14];
    const float* ar3 = (const float*)d_in[15];
    const float* bg3 = (const float*)d_in[16];
    const float* sw  = (const float*)d_in[17];
    const float* sb  = (const float*)d_in[18];
    const float* lw1 = (const float*)d_in[19];
    const float* lb1 = (const float*)d_in[20];
    const float* lw2 = (const float*)d_in[21];
    const float* lb2 = (const float*)d_in[22];
    const float* lw3 = (const float*)d_in[23];
    const float* lb3 = (const float*)d_in[24];
    float* out = (float*)d_out;

    const int scan_blocks = (NN + 1023) / 1024;  // 98

    // CSR by dst (rebuilt every call: no caching allowed)
    zero_deg_kernel<<<(NN + 255) / 256, 256>>>();
    hist_kernel<<<(EE + 255) / 256, 256>>>(dst);
    scan_local_kernel<<<scan_blocks, 1024>>>();
    scan_bsum_kernel<<<1, 128>>>(scan_blocks);
    scan_finalize_kernel<<<scan_blocks, 1024>>>();
    scatter_kernel<<<(EE + 255) / 256, 256>>>(src, dst);

    dim3 ggrid(2, (NN + 127) / 128);
    const int nwb = NN / 8;  // 12500 blocks of 8 warps

    // layer 1
    gemm_kernel<<<ggrid, 256>>>(feats_node, 0, W1, 64);
    elr_kernel<<<nwb, 256>>>(al1, ar1);
    aggregate_kernel<<<nwb, 256>>>(bg1);
    // layer 2
    gemm_kernel<<<ggrid, 256>>>(nullptr, 1, W2, 256);
    elr_kernel<<<nwb, 256>>>(al2, ar2);
    aggregate_kernel<<<nwb, 256>>>(bg2);
    // layer 3
    gemm_kernel<<<ggrid, 256>>>(nullptr, 1, W3, 256);
    elr_kernel<<<nwb, 256>>>(al3, ar3);
    aggregate_kernel<<<nwb, 256>>>(bg3);

    // readout + MLP
    score_kernel<<<nwb, 256>>>(sw, sb);
    boundary_kernel<<<(NN + 255) / 256, 256>>>(ng);
    readout_kernel<<<BB, 256>>>(feats_graph);
    mlp_kernel<<<BB, 128>>>(lw1, lb1, lw2, lb2, lw3, lb3, out);
}

// round 14
// speedup vs baseline: 1.1078x; 1.0006x over previous
#include <cuda_runtime.h>

#define NN 100000
#define EE 1600000
#define BB 512
#define HH 4
#define DD 64
#define HD 256
#define EXTRA 16
#define YW (HD + EXTRA)   // 272
#define KC 16             // GEMM K-chunk

// ---------------- scratch (no allocations allowed) ----------------
__device__ __align__(16) float g_h[(size_t)NN * HD];   // GEMM output h
__device__ __align__(16) float g_x[(size_t)NN * HD];   // layer activations
__device__ __align__(16) float g_el[NN * HH];
__device__ __align__(16) float g_er[NN * HH];
__device__ int   g_deg[NN];
__device__ int   g_rowstart[NN + 1];
__device__ int   g_cursor[NN];
__device__ int   g_col[EE];          // src node per CSR slot (grouped by dst)
__device__ float g_w[NN];            // readout scores
__device__ int   g_gstart[BB + 1];
__device__ __align__(16) float g_y[BB * YW];
__device__ int   g_bsum[128];
__device__ int   g_boff[128];

__device__ __forceinline__ float seluf(float v) {
    const float a = 1.6732632423543772f, s = 1.0507009873554805f;
    return v > 0.f ? s * v : s * a * (expf(v) - 1.f);
}
__device__ __forceinline__ float lrelu(float v) { return v > 0.f ? v : 0.2f * v; }

// packed fp32x2 helpers (Blackwell FFMA2 path — only reachable via PTX)
__device__ __forceinline__ unsigned long long ffma2(unsigned long long a,
                                                    unsigned long long b,
                                                    unsigned long long c) {
    unsigned long long d;
    asm("fma.rn.f32x2 %0, %1, %2, %3;" : "=l"(d) : "l"(a), "l"(b), "l"(c));
    return d;
}
__device__ __forceinline__ unsigned long long pack2(float lo, float hi) {
    unsigned long long v;
    asm("mov.b64 %0, {%1, %2};" : "=l"(v) : "f"(lo), "f"(hi));
    return v;
}
__device__ __forceinline__ void unpack2(unsigned long long v, float& lo, float& hi) {
    asm("mov.b64 {%0, %1}, %2;" : "=f"(lo), "=f"(hi) : "l"(v));
}

// ---------------- CSR build ----------------
__global__ void zero_deg_kernel() {
    int i = blockIdx.x * blockDim.x + threadIdx.x;
    if (i < NN) g_deg[i] = 0;
}
__global__ void hist_kernel(const int* __restrict__ dst) {
    int e = blockIdx.x * blockDim.x + threadIdx.x;
    if (e < EE) atomicAdd(&g_deg[dst[e]], 1);
}
// 3-phase parallel scan of g_deg -> g_rowstart (inclusive at i+1) + g_cursor (exclusive)
__global__ __launch_bounds__(1024) void scan_local_kernel() {
    __shared__ int sm[1024];
    int i = blockIdx.x * 1024 + threadIdx.x;
    int v = (i < NN) ? g_deg[i] : 0;
    sm[threadIdx.x] = v;
    __syncthreads();
    for (int off = 1; off < 1024; off <<= 1) {
        int t = (threadIdx.x >= off) ? sm[threadIdx.x - off] : 0;
        __syncthreads();
        sm[threadIdx.x] += t;
        __syncthreads();
    }
    if (i < NN) g_cursor[i] = sm[threadIdx.x];   // local inclusive
    if (threadIdx.x == 1023) g_bsum[blockIdx.x] = sm[1023];
}
__global__ __launch_bounds__(128) void scan_bsum_kernel(int nblocks) {
    __shared__ int sm[128];
    int v = (threadIdx.x < nblocks) ? g_bsum[threadIdx.x] : 0;
    sm[threadIdx.x] = v;
    __syncthreads();
    for (int off = 1; off < 128; off <<= 1) {
        int t = (threadIdx.x >= off) ? sm[threadIdx.x - off] : 0;
        __syncthreads();
        sm[threadIdx.x] += t;
        __syncthreads();
    }
    g_boff[threadIdx.x] = sm[threadIdx.x] - v;   // exclusive
}
__global__ __launch_bounds__(1024) void scan_finalize_kernel() {
    int i = blockIdx.x * 1024 + threadIdx.x;
    if (i >= NN) return;
    int inc = g_cursor[i] + g_boff[blockIdx.x];
    g_rowstart[i + 1] = inc;
    g_cursor[i] = inc - g_deg[i];
    if (i == 0) g_rowstart[0] = 0;
}
__global__ void scatter_kernel(const int* __restrict__ src, const int* __restrict__ dst) {
    int e = blockIdx.x * blockDim.x + threadIdx.x;
    if (e < EE) {
        int pos = atomicAdd(&g_cursor[dst[e]], 1);
        g_col[pos] = src[e];
    }
}

// ---------------- GEMM: C[M,256] = A[M,K] @ B[K,256]  (C = g_h), packed f32x2 ----------------
__global__ __launch_bounds__(256) void gemm_kernel(const float* __restrict__ A_ext,
                                                   int use_gx,
                                                   const float* __restrict__ B,
                                                   int Kdim) {
    const float* __restrict__ A = use_gx ? g_x : A_ext;
    __shared__ float As[KC][128];
    __shared__ float Bs[KC][128];
    int tid = threadIdx.x;
    int bm = blockIdx.y * 128;
    int bn = blockIdx.x * 128;
    int a_row = tid >> 1;            // 0..127
    int a_k   = (tid & 1) << 3;      // 0 or 8
    int b_k   = tid >> 4;            // 0..15
    int b_n   = (tid & 15) << 3;     // 0..120
    int ty = tid >> 4, tx = tid & 15;

    unsigned long long acc2[8][4];
#pragma unroll
    for (int i = 0; i < 8; i++)
#pragma unroll
        for (int j = 0; j < 4; j++) acc2[i][j] = 0ull;

    int gr_a = bm + a_row;
    bool a_ok = gr_a < NN;
    const float* Arow = A + (size_t)gr_a * Kdim;

    for (int k0 = 0; k0 < Kdim; k0 += KC) {
        float4 av0 = make_float4(0.f, 0.f, 0.f, 0.f), av1 = av0;
        if (a_ok) {
            av0 = *(const float4*)(Arow + k0 + a_k);
            av1 = *(const float4*)(Arow + k0 + a_k + 4);
        }
        As[a_k + 0][a_row] = av0.x; As[a_k + 1][a_row] = av0.y;
        As[a_k + 2][a_row] = av0.z; As[a_k + 3][a_row] = av0.w;
        As[a_k + 4][a_row] = av1.x; As[a_k + 5][a_row] = av1.y;
        As[a_k + 6][a_row] = av1.z; As[a_k + 7][a_row] = av1.w;
        const float* Brow = B + (size_t)(k0 + b_k) * 256 + bn + b_n;
        *(float4*)&Bs[b_k][b_n]     = *(const float4*)(Brow);
        *(float4*)&Bs[b_k][b_n + 4] = *(const float4*)(Brow + 4);
        __syncthreads();
#pragma unroll
        for (int k = 0; k < KC; k++) {
            float a_[8];
            *(float4*)&a_[0] = *(const float4*)&As[k][ty * 8];
            *(float4*)&a_[4] = *(const float4*)&As[k][ty * 8 + 4];
            ulonglong2 blo = *(const ulonglong2*)&Bs[k][tx * 8];
            ulonglong2 bhi = *(const ulonglong2*)&Bs[k][tx * 8 + 4];
            unsigned long long b2[4] = {blo.x, blo.y, bhi.x, bhi.y};
#pragma unroll
            for (int i = 0; i < 8; i++) {
                unsigned long long pa = pack2(a_[i], a_[i]);
#pragma unroll
                for (int j = 0; j < 4; j++) acc2[i][j] = ffma2(pa, b2[j], acc2[i][j]);
            }
        }
        __syncthreads();
    }
#pragma unroll
    for (int i = 0; i < 8; i++) {
        int gr = bm + ty * 8 + i;
        if (gr < NN) {
            float c[8];
#pragma unroll
            for (int j = 0; j < 4; j++) unpack2(acc2[i][j], c[2 * j], c[2 * j + 1]);
            float* cp = g_h + (size_t)gr * 256 + bn + tx * 8;
            *(float4*)cp       = make_float4(c[0], c[1], c[2], c[3]);
            *(float4*)(cp + 4) = make_float4(c[4], c[5], c[6], c[7]);
        }
    }
}

// ---------------- per-node attention logits el/er ----------------
__global__ __launch_bounds__(256) void elr_kernel(const float* __restrict__ al,
                                                  const float* __restrict__ ar) {
    int lane = threadIdx.x & 31;
    int v = blockIdx.x * 8 + (threadIdx.x >> 5);
    if (v >= NN) return;
    const float* hrow = g_h + (size_t)v * HD;
    float pl[4] = {0.f, 0.f, 0.f, 0.f}, pr[4] = {0.f, 0.f, 0.f, 0.f};
#pragma unroll
    for (int k = 0; k < 8; k++) {
        int dim = lane + 32 * k;
        float hv = hrow[dim];
        pl[k >> 1] += hv * al[dim];
        pr[k >> 1] += hv * ar[dim];
    }
#pragma unroll
    for (int off = 16; off; off >>= 1) {
#pragma unroll
        for (int h = 0; h < 4; h++) {
            pl[h] += __shfl_xor_sync(0xffffffffu, pl[h], off);
            pr[h] += __shfl_xor_sync(0xffffffffu, pr[h], off);
        }
    }
    if (lane == 0) {
        ((float4*)g_el)[v] = make_float4(pl[0], pl[1], pl[2], pl[3]);
        ((float4*)g_er)[v] = make_float4(pr[0], pr[1], pr[2], pr[3]);
    }
}

// ---------------- segment-softmax + weighted aggregate (one warp per dst node) ----------------
__global__ __launch_bounds__(256) void aggregate_kernel(const float* __restrict__ bias) {
    __shared__ int    s_src[8][32];
    __shared__ float4 s_w[8][32];
    int lane = threadIdx.x & 31;
    int wslot = threadIdx.x >> 5;
    int v = blockIdx.x * 8 + wslot;
    if (v >= NN) return;
    int start = g_rowstart[v], end = g_rowstart[v + 1];
    float4 erv = ((const float4*)g_er)[v];

    // pass 1: per-head max
    float m0 = -1e30f, m1 = -1e30f, m2 = -1e30f, m3 = -1e30f;
    for (int i = start + lane; i < end; i += 32) {
        int s = g_col[i];
        float4 elv = ((const float4*)g_el)[s];
        m0 = fmaxf(m0, lrelu(elv.x + erv.x));
        m1 = fmaxf(m1, lrelu(elv.y + erv.y));
        m2 = fmaxf(m2, lrelu(elv.z + erv.z));
        m3 = fmaxf(m3, lrelu(elv.w + erv.w));
    }
#pragma unroll
    for (int off = 16; off; off >>= 1) {
        m0 = fmaxf(m0, __shfl_xor_sync(0xffffffffu, m0, off));
        m1 = fmaxf(m1, __shfl_xor_sync(0xffffffffu, m1, off));
        m2 = fmaxf(m2, __shfl_xor_sync(0xffffffffu, m2, off));
        m3 = fmaxf(m3, __shfl_xor_sync(0xffffffffu, m3, off));
    }

    // pass 2: exp weights + weighted gather of h[src]
    float acc[8];
#pragma unroll
    for (int k = 0; k < 8; k++) acc[k] = 0.f;
    float den0 = 0.f, den1 = 0.f, den2 = 0.f, den3 = 0.f;

    for (int base = start; base < end; base += 32) {
        int idx = base + lane;
        if (idx < end) {
            int s = g_col[idx];
            float4 elv = ((const float4*)g_el)[s];
            float4 wv;
            wv.x = expf(lrelu(elv.x + erv.x) - m0);
            wv.y = expf(lrelu(elv.y + erv.y) - m1);
            wv.z = expf(lrelu(elv.z + erv.z) - m2);
            wv.w = expf(lrelu(elv.w + erv.w) - m3);
            s_src[wslot][lane] = s;
            s_w[wslot][lane] = wv;
        }
        __syncwarp();
        int cnt = min(32, end - base);
        for (int j = 0; j < cnt; j++) {
            int s = s_src[wslot][j];
            float4 wv = s_w[wslot][j];
            den0 += wv.x; den1 += wv.y; den2 += wv.z; den3 += wv.w;
            const float* hrow = g_h + (size_t)s * HD;
            float warr[4] = {wv.x, wv.y, wv.z, wv.w};
#pragma unroll
            for (int k = 0; k < 8; k++)
                acc[k] += warr[k >> 1] * hrow[lane + 32 * k];
        }
        __syncwarp();
    }
    float den[4] = {den0, den1, den2, den3};
    float* xrow = g_x + (size_t)v * HD;
#pragma unroll
    for (int k = 0; k < 8; k++) {
        int dim = lane + 32 * k;
        float val = acc[k] / fmaxf(den[k >> 1], 1e-9f) + bias[dim];
        xrow[dim] = seluf(val);
    }
}

// ---------------- readout ----------------
__global__ __launch_bounds__(256) void score_kernel(const float* __restrict__ sw,
                                                    const float* __restrict__ sb) {
    int lane = threadIdx.x & 31;
    int v = blockIdx.x * 8 + (threadIdx.x >> 5);
    if (v >= NN) return;
    const float* xr = g_x + (size_t)v * HD;
    float p = 0.f;
#pragma unroll
    for (int k = 0; k < 8; k++) { int dim = lane + 32 * k; p += xr[dim] * sw[dim]; }
#pragma unroll
    for (int off = 16; off; off >>= 1) p += __shfl_xor_sync(0xffffffffu, p, off);
    if (lane == 0) g_w[v] = 1.f / (1.f + expf(-(p + sb[0])));
}

__global__ void boundary_kernel(const int* __restrict__ ng) {
    int i = blockIdx.x * blockDim.x + threadIdx.x;
    if (i >= NN) return;
    int g = ng[i];
    int pg = (i == 0) ? -1 : ng[i - 1];
    for (int gg = pg + 1; gg <= g; gg++) g_gstart[gg] = i;
    if (i == NN - 1)
        for (int gg = g + 1; gg <= BB; gg++) g_gstart[gg] = NN;
}

__global__ __launch_bounds__(256) void readout_kernel(const float* __restrict__ fg) {
    int g = blockIdx.x, d = threadIdx.x;
    int s = g_gstart[g], e = g_gstart[g + 1];
    float num = 0.f, ws = 0.f;
    for (int i = s; i < e; i++) {
        float wv = g_w[i];
        num += wv * g_x[(size_t)i * HD + d];
        ws += wv;
    }
    g_y[g * YW + d] = num / fmaxf(ws, 1e-9f);
    if (d < EXTRA) g_y[g * YW + HD + d] = fg[g * EXTRA + d];
}

// ---------------- MLP head ----------------
__global__ __launch_bounds__(128) void mlp_kernel(const float* __restrict__ lw1,
                                                  const float* __restrict__ lb1,
                                                  const float* __restrict__ lw2,
                                                  const float* __restrict__ lb2,
                                                  const float* __restrict__ lw3,
                                                  const float* __restrict__ lb3,
                                                  float* __restrict__ out) {
    __shared__ float yrow[YW];
    __shared__ float h1[128];
    __shared__ float h2[64];
    int g = blockIdx.x, t = threadIdx.x;
    const float* y = g_y + g * YW;
    yrow[t] = y[t];
    yrow[t + 128] = y[t + 128];
    if (t < 16) yrow[t + 256] = y[t + 256];
    __syncthreads();
    float s = lb1[t];
#pragma unroll 8
    for (int j = 0; j < YW; j++) s += yrow[j] * lw1[j * 128 + t];
    h1[t] = seluf(s);
    __syncthreads();
    if (t < 64) {
        float s2 = lb2[t];
#pragma unroll 8
        for (int j = 0; j < 128; j++) s2 += h1[j] * lw2[j * 64 + t];
        h2[t] = seluf(s2);
    }
    __syncthreads();
    if (t < 32) {
        float p = h2[t] * lw3[t] + h2[t + 32] * lw3[t + 32];
#pragma unroll
        for (int off = 16; off; off >>= 1) p += __shfl_xor_sync(0xffffffffu, p, off);
        if (t == 0) out[g] = p + lb3[0];
    }
}

// ---------------- launch ----------------
extern "C" void kernel_launch(void* const* d_in, const int* in_sizes, int n_in,
                              void* d_out, int out_size) {
    const int*   src = (const int*)d_in[0];
    const int*   dst = (const int*)d_in[1];
    const int*   ng  = (const int*)d_in[2];
    const float* feats_node  = (const float*)d_in[3];
    const float* feats_graph = (const float*)d_in[4];
    const float* W1  = (const float*)d_in[5];
    const float* al1 = (const float*)d_in[6];
    const float* ar1 = (const float*)d_in[7];
    const float* bg1 = (const float*)d_in[8];
    const float* W2  = (const float*)d_in[9];
    const float* al2 = (const float*)d_in[10];
    const float* ar2 = (const float*)d_in[11];
    const float* bg2 = (const float*)d_in[12];
    const float* W3  = (const float*)d_in[13];
    const float* al3 = (const float*)d_in[14];
    const float* ar3 = (const float*)d_in[15];
    const float* bg3 = (const float*)d_in[16];
    const float* sw  = (const float*)d_in[17];
    const float* sb  = (const float*)d_in[18];
    const float* lw1 = (const float*)d_in[19];
    const float* lb1 = (const float*)d_in[20];
    const float* lw2 = (const float*)d_in[21];
    const float* lb2 = (const float*)d_in[22];
    const float* lw3 = (const float*)d_in[23];
    const float* lb3 = (const float*)d_in[24];
    float* out = (float*)d_out;

    const int scan_blocks = (NN + 1023) / 1024;  // 98

    // CSR by dst (rebuilt every call: no caching allowed)
    zero_deg_kernel<<<(NN + 255) / 256, 256>>>();
    hist_kernel<<<(EE + 255) / 256, 256>>>(dst);
    scan_local_kernel<<<scan_blocks, 1024>>>();
    scan_bsum_kernel<<<1, 128>>>(scan_blocks);
    scan_finalize_kernel<<<scan_blocks, 1024>>>();
    scatter_kernel<<<(EE + 255) / 256, 256>>>(src, dst);

    dim3 ggrid(2, (NN + 127) / 128);
    const int nwb = NN / 8;  // 12500 blocks of 8 warps

    // layer 1
    gemm_kernel<<<ggrid, 256>>>(feats_node, 0, W1, 64);
    elr_kernel<<<nwb, 256>>>(al1, ar1);
    aggregate_kernel<<<nwb, 256>>>(bg1);
    // layer 2
    gemm_kernel<<<ggrid, 256>>>(nullptr, 1, W2, 256);
    elr_kernel<<<nwb, 256>>>(al2, ar2);
    aggregate_kernel<<<nwb, 256>>>(bg2);
    // layer 3
    gemm_kernel<<<ggrid, 256>>>(nullptr, 1, W3, 256);
    elr_kernel<<<nwb, 256>>>(al3, ar3);
    aggregate_kernel<<<nwb, 256>>>(bg3);

    // readout + MLP
    score_kernel<<<nwb, 256>>>(sw, sb);
    boundary_kernel<<<(NN + 255) / 256, 256>>>(ng);
    readout_kernel<<<BB, 256>>>(feats_graph);
    mlp_kernel<<<BB, 128>>>(lw1, lb1, lw2, lb2, lw3, lb3, out);
}

// round 15
// speedup vs baseline: 1.1081x; 1.0003x over previous
#include <cuda_runtime.h>

#define NN 100000
#define EE 1600000
#define BB 512
#define HH 4
#define DD 64
#define HD 256
#define EXTRA 16
#define YW (HD + EXTRA)   // 272
#define KC 16             // GEMM K-chunk

// ---------------- scratch (no allocations allowed) ----------------
__device__ __align__(16) float g_h[(size_t)NN * HD];   // GEMM output h
__device__ __align__(16) float g_x[(size_t)NN * HD];   // layer activations
__device__ __align__(16) float g_el[NN * HH];
__device__ __align__(16) float g_er[NN * HH];
__device__ int   g_deg[NN];
__device__ int   g_rowstart[NN + 1];
__device__ int   g_cursor[NN];
__device__ int   g_col[EE];          // src node per CSR slot (grouped by dst)
__device__ float g_w[NN];            // readout scores
__device__ int   g_gstart[BB + 1];
__device__ __align__(16) float g_y[BB * YW];
__device__ int   g_bsum[128];
__device__ int   g_boff[128];

__device__ __forceinline__ float seluf(float v) {
    const float a = 1.6732632423543772f, s = 1.0507009873554805f;
    return v > 0.f ? s * v : s * a * (expf(v) - 1.f);
}
__device__ __forceinline__ float lrelu(float v) { return v > 0.f ? v : 0.2f * v; }

// packed fp32x2 helpers (Blackwell FFMA2 path — only reachable via PTX)
__device__ __forceinline__ unsigned long long ffma2(unsigned long long a,
                                                    unsigned long long b,
                                                    unsigned long long c) {
    unsigned long long d;
    asm("fma.rn.f32x2 %0, %1, %2, %3;" : "=l"(d) : "l"(a), "l"(b), "l"(c));
    return d;
}
__device__ __forceinline__ unsigned long long pack2(float lo, float hi) {
    unsigned long long v;
    asm("mov.b64 %0, {%1, %2};" : "=l"(v) : "f"(lo), "f"(hi));
    return v;
}
__device__ __forceinline__ void unpack2(unsigned long long v, float& lo, float& hi) {
    asm("mov.b64 {%0, %1}, %2;" : "=f"(lo), "=f"(hi) : "l"(v));
}

// ---------------- CSR build ----------------
__global__ void zero_deg_kernel() {
    int i = blockIdx.x * blockDim.x + threadIdx.x;
    if (i < NN) g_deg[i] = 0;
}
__global__ void hist_kernel(const int* __restrict__ dst) {
    int e = blockIdx.x * blockDim.x + threadIdx.x;
    if (e < EE) atomicAdd(&g_deg[dst[e]], 1);
}
// 3-phase parallel scan of g_deg -> g_rowstart (inclusive at i+1) + g_cursor (exclusive)
__global__ __launch_bounds__(1024) void scan_local_kernel() {
    __shared__ int sm[1024];
    int i = blockIdx.x * 1024 + threadIdx.x;
    int v = (i < NN) ? g_deg[i] : 0;
    sm[threadIdx.x] = v;
    __syncthreads();
    for (int off = 1; off < 1024; off <<= 1) {
        int t = (threadIdx.x >= off) ? sm[threadIdx.x - off] : 0;
        __syncthreads();
        sm[threadIdx.x] += t;
        __syncthreads();
    }
    if (i < NN) g_cursor[i] = sm[threadIdx.x];   // local inclusive
    if (threadIdx.x == 1023) g_bsum[blockIdx.x] = sm[1023];
}
__global__ __launch_bounds__(128) void scan_bsum_kernel(int nblocks) {
    __shared__ int sm[128];
    int v = (threadIdx.x < nblocks) ? g_bsum[threadIdx.x] : 0;
    sm[threadIdx.x] = v;
    __syncthreads();
    for (int off = 1; off < 128; off <<= 1) {
        int t = (threadIdx.x >= off) ? sm[threadIdx.x - off] : 0;
        __syncthreads();
        sm[threadIdx.x] += t;
        __syncthreads();
    }
    g_boff[threadIdx.x] = sm[threadIdx.x] - v;   // exclusive
}
__global__ __launch_bounds__(1024) void scan_finalize_kernel() {
    int i = blockIdx.x * 1024 + threadIdx.x;
    if (i >= NN) return;
    int inc = g_cursor[i] + g_boff[blockIdx.x];
    g_rowstart[i + 1] = inc;
    g_cursor[i] = inc - g_deg[i];
    if (i == 0) g_rowstart[0] = 0;
}
__global__ void scatter_kernel(const int* __restrict__ src, const int* __restrict__ dst) {
    int e = blockIdx.x * blockDim.x + threadIdx.x;
    if (e < EE) {
        int pos = atomicAdd(&g_cursor[dst[e]], 1);
        g_col[pos] = src[e];
    }
}

// ---------------- GEMM: C[M,256] = A[M,K] @ B[K,256]  (C = g_h), packed f32x2 ----------------
__global__ __launch_bounds__(256) void gemm_kernel(const float* __restrict__ A_ext,
                                                   int use_gx,
                                                   const float* __restrict__ B,
                                                   int Kdim) {
    const float* __restrict__ A = use_gx ? g_x : A_ext;
    __shared__ float As[KC][128];
    __shared__ float Bs[KC][128];
    int tid = threadIdx.x;
    int bm = blockIdx.y * 128;
    int bn = blockIdx.x * 128;
    int a_row = tid >> 1;            // 0..127
    int a_k   = (tid & 1) << 3;      // 0 or 8
    int b_k   = tid >> 4;            // 0..15
    int b_n   = (tid & 15) << 3;     // 0..120
    int ty = tid >> 4, tx = tid & 15;

    unsigned long long acc2[8][4];
#pragma unroll
    for (int i = 0; i < 8; i++)
#pragma unroll
        for (int j = 0; j < 4; j++) acc2[i][j] = 0ull;

    int gr_a = bm + a_row;
    bool a_ok = gr_a < NN;
    const float* Arow = A + (size_t)gr_a * Kdim;

    for (int k0 = 0; k0 < Kdim; k0 += KC) {
        float4 av0 = make_float4(0.f, 0.f, 0.f, 0.f), av1 = av0;
        if (a_ok) {
            av0 = *(const float4*)(Arow + k0 + a_k);
            av1 = *(const float4*)(Arow + k0 + a_k + 4);
        }
        As[a_k + 0][a_row] = av0.x; As[a_k + 1][a_row] = av0.y;
        As[a_k + 2][a_row] = av0.z; As[a_k + 3][a_row] = av0.w;
        As[a_k + 4][a_row] = av1.x; As[a_k + 5][a_row] = av1.y;
        As[a_k + 6][a_row] = av1.z; As[a_k + 7][a_row] = av1.w;
        const float* Brow = B + (size_t)(k0 + b_k) * 256 + bn + b_n;
        *(float4*)&Bs[b_k][b_n]     = *(const float4*)(Brow);
        *(float4*)&Bs[b_k][b_n + 4] = *(const float4*)(Brow + 4);
        __syncthreads();
#pragma unroll
        for (int k = 0; k < KC; k++) {
            float a_[8];
            *(float4*)&a_[0] = *(const float4*)&As[k][ty * 8];
            *(float4*)&a_[4] = *(const float4*)&As[k][ty * 8 + 4];
            ulonglong2 blo = *(const ulonglong2*)&Bs[k][tx * 8];
            ulonglong2 bhi = *(const ulonglong2*)&Bs[k][tx * 8 + 4];
            unsigned long long b2[4] = {blo.x, blo.y, bhi.x, bhi.y};
#pragma unroll
            for (int i = 0; i < 8; i++) {
                unsigned long long pa = pack2(a_[i], a_[i]);
#pragma unroll
                for (int j = 0; j < 4; j++) acc2[i][j] = ffma2(pa, b2[j], acc2[i][j]);
            }
        }
        __syncthreads();
    }
#pragma unroll
    for (int i = 0; i < 8; i++) {
        int gr = bm + ty * 8 + i;
        if (gr < NN) {
            float c[8];
#pragma unroll
            for (int j = 0; j < 4; j++) unpack2(acc2[i][j], c[2 * j], c[2 * j + 1]);
            float* cp = g_h + (size_t)gr * 256 + bn + tx * 8;
            *(float4*)cp       = make_float4(c[0], c[1], c[2], c[3]);
            *(float4*)(cp + 4) = make_float4(c[4], c[5], c[6], c[7]);
        }
    }
}

// ---------------- per-node attention logits el/er ----------------
__global__ __launch_bounds__(256) void elr_kernel(const float* __restrict__ al,
                                                  const float* __restrict__ ar) {
    int lane = threadIdx.x & 31;
    int v = blockIdx.x * 8 + (threadIdx.x >> 5);
    if (v >= NN) return;
    const float* hrow = g_h + (size_t)v * HD;
    float pl[4] = {0.f, 0.f, 0.f, 0.f}, pr[4] = {0.f, 0.f, 0.f, 0.f};
#pragma unroll
    for (int k = 0; k < 8; k++) {
        int dim = lane + 32 * k;
        float hv = hrow[dim];
        pl[k >> 1] += hv * al[dim];
        pr[k >> 1] += hv * ar[dim];
    }
#pragma unroll
    for (int off = 16; off; off >>= 1) {
#pragma unroll
        for (int h = 0; h < 4; h++) {
            pl[h] += __shfl_xor_sync(0xffffffffu, pl[h], off);
            pr[h] += __shfl_xor_sync(0xffffffffu, pr[h], off);
        }
    }
    if (lane == 0) {
        ((float4*)g_el)[v] = make_float4(pl[0], pl[1], pl[2], pl[3]);
        ((float4*)g_er)[v] = make_float4(pr[0], pr[1], pr[2], pr[3]);
    }
}

// ---------------- segment-softmax + weighted aggregate (one warp per dst node) ----------------
__global__ __launch_bounds__(256) void aggregate_kernel(const float* __restrict__ bias) {
    __shared__ int    s_src[8][32];
    __shared__ float4 s_w[8][32];
    int lane = threadIdx.x & 31;
    int wslot = threadIdx.x >> 5;
    int v = blockIdx.x * 8 + wslot;
    if (v >= NN) return;
    int start = g_rowstart[v], end = g_rowstart[v + 1];
    float4 erv = ((const float4*)g_er)[v];

    // pass 1: per-head max
    float m0 = -1e30f, m1 = -1e30f, m2 = -1e30f, m3 = -1e30f;
    for (int i = start + lane; i < end; i += 32) {
        int s = g_col[i];
        float4 elv = ((const float4*)g_el)[s];
        m0 = fmaxf(m0, lrelu(elv.x + erv.x));
        m1 = fmaxf(m1, lrelu(elv.y + erv.y));
        m2 = fmaxf(m2, lrelu(elv.z + erv.z));
        m3 = fmaxf(m3, lrelu(elv.w + erv.w));
    }
#pragma unroll
    for (int off = 16; off; off >>= 1) {
        m0 = fmaxf(m0, __shfl_xor_sync(0xffffffffu, m0, off));
        m1 = fmaxf(m1, __shfl_xor_sync(0xffffffffu, m1, off));
        m2 = fmaxf(m2, __shfl_xor_sync(0xffffffffu, m2, off));
        m3 = fmaxf(m3, __shfl_xor_sync(0xffffffffu, m3, off));
    }

    // pass 2: exp weights + weighted gather of h[src]
    float acc[8];
#pragma unroll
    for (int k = 0; k < 8; k++) acc[k] = 0.f;
    float den0 = 0.f, den1 = 0.f, den2 = 0.f, den3 = 0.f;

    for (int base = start; base < end; base += 32) {
        int idx = base + lane;
        if (idx < end) {
            int s = g_col[idx];
            float4 elv = ((const float4*)g_el)[s];
            float4 wv;
            wv.x = expf(lrelu(elv.x + erv.x) - m0);
            wv.y = expf(lrelu(elv.y + erv.y) - m1);
            wv.z = expf(lrelu(elv.z + erv.z) - m2);
            wv.w = expf(lrelu(elv.w + erv.w) - m3);
            s_src[wslot][lane] = s;
            s_w[wslot][lane] = wv;
        }
        __syncwarp();
        int cnt = min(32, end - base);
        for (int j = 0; j < cnt; j++) {
            int s = s_src[wslot][j];
            float4 wv = s_w[wslot][j];
            den0 += wv.x; den1 += wv.y; den2 += wv.z; den3 += wv.w;
            const float* hrow = g_h + (size_t)s * HD;
            float warr[4] = {wv.x, wv.y, wv.z, wv.w};
#pragma unroll
            for (int k = 0; k < 8; k++)
                acc[k] += warr[k >> 1] * hrow[lane + 32 * k];
        }
        __syncwarp();
    }
    float den[4] = {den0, den1, den2, den3};
    float* xrow = g_x + (size_t)v * HD;
#pragma unroll
    for (int k = 0; k < 8; k++) {
        int dim = lane + 32 * k;
        float val = acc[k] / fmaxf(den[k >> 1], 1e-9f) + bias[dim];
        xrow[dim] = seluf(val);
    }
}

// ---------------- readout ----------------
__global__ __launch_bounds__(256) void score_kernel(const float* __restrict__ sw,
                                                    const float* __restrict__ sb) {
    int lane = threadIdx.x & 31;
    int v = blockIdx.x * 8 + (threadIdx.x >> 5);
    if (v >= NN) return;
    const float* xr = g_x + (size_t)v * HD;
    float p = 0.f;
#pragma unroll
    for (int k = 0; k < 8; k++) { int dim = lane + 32 * k; p += xr[dim] * sw[dim]; }
#pragma unroll
    for (int off = 16; off; off >>= 1) p += __shfl_xor_sync(0xffffffffu, p, off);
    if (lane == 0) g_w[v] = 1.f / (1.f + expf(-(p + sb[0])));
}

__global__ void boundary_kernel(const int* __restrict__ ng) {
    int i = blockIdx.x * blockDim.x + threadIdx.x;
    if (i >= NN) return;
    int g = ng[i];
    int pg = (i == 0) ? -1 : ng[i - 1];
    for (int gg = pg + 1; gg <= g; gg++) g_gstart[gg] = i;
    if (i == NN - 1)
        for (int gg = g + 1; gg <= BB; gg++) g_gstart[gg] = NN;
}

__global__ __launch_bounds__(256) void readout_kernel(const float* __restrict__ fg) {
    int g = blockIdx.x, d = threadIdx.x;
    int s = g_gstart[g], e = g_gstart[g + 1];
    float num = 0.f, ws = 0.f;
    for (int i = s; i < e; i++) {
        float wv = g_w[i];
        num += wv * g_x[(size_t)i * HD + d];
        ws += wv;
    }
    g_y[g * YW + d] = num / fmaxf(ws, 1e-9f);
    if (d < EXTRA) g_y[g * YW + HD + d] = fg[g * EXTRA + d];
}

// ---------------- MLP head ----------------
__global__ __launch_bounds__(128) void mlp_kernel(const float* __restrict__ lw1,
                                                  const float* __restrict__ lb1,
                                                  const float* __restrict__ lw2,
                                                  const float* __restrict__ lb2,
                                                  const float* __restrict__ lw3,
                                                  const float* __restrict__ lb3,
                                                  float* __restrict__ out) {
    __shared__ float yrow[YW];
    __shared__ float h1[128];
    __shared__ float h2[64];
    int g = blockIdx.x, t = threadIdx.x;
    const float* y = g_y + g * YW;
    yrow[t] = y[t];
    yrow[t + 128] = y[t + 128];
    if (t < 16) yrow[t + 256] = y[t + 256];
    __syncthreads();
    float s = lb1[t];
#pragma unroll 8
    for (int j = 0; j < YW; j++) s += yrow[j] * lw1[j * 128 + t];
    h1[t] = seluf(s);
    __syncthreads();
    if (t < 64) {
        float s2 = lb2[t];
#pragma unroll 8
        for (int j = 0; j < 128; j++) s2 += h1[j] * lw2[j * 64 + t];
        h2[t] = seluf(s2);
    }
    __syncthreads();
    if (t < 32) {
        float p = h2[t] * lw3[t] + h2[t + 32] * lw3[t + 32];
#pragma unroll
        for (int off = 16; off; off >>= 1) p += __shfl_xor_sync(0xffffffffu, p, off);
        if (t == 0) out[g] = p + lb3[0];
    }
}

// ---------------- launch ----------------
extern "C" void kernel_launch(void* const* d_in, const int* in_sizes, int n_in,
                              void* d_out, int out_size) {
    const int*   src = (const int*)d_in[0];
    const int*   dst = (const int*)d_in[1];
    const int*   ng  = (const int*)d_in[2];
    const float* feats_node  = (const float*)d_in[3];
    const float* feats_graph = (const float*)d_in[4];
    const float* W1  = (const float*)d_in[5];
    const float* al1 = (const float*)d_in[6];
    const float* ar1 = (const float*)d_in[7];
    const float* bg1 = (const float*)d_in[8];
    const float* W2  = (const float*)d_in[9];
    const float* al2 = (const float*)d_in[10];
    const float* ar2 = (const float*)d_in[11];
    const float* bg2 = (const float*)d_in[12];
    const float* W3  = (const float*)d_in[13];
    const float* al3 = (const float*)d_in[14];
    const float* ar3 = (const float*)d_in[15];
    const float* bg3 = (const float*)d_in[16];
    const float* sw  = (const float*)d_in[17];
    const float* sb  = (const float*)d_in[18];
    const float* lw1 = (const float*)d_in[19];
    const float* lb1 = (const float*)d_in[20];
    const float* lw2 = (const float*)d_in[21];
    const float* lb2 = (const float*)d_in[22];
    const float* lw3 = (const float*)d_in[23];
    const float* lb3 = (const float*)d_in[24];
    float* out = (float*)d_out;

    const int scan_blocks = (NN + 1023) / 1024;  // 98

    // CSR by dst (rebuilt every call: no caching allowed)
    zero_deg_kernel<<<(NN + 255) / 256, 256>>>();
    hist_kernel<<<(EE + 255) / 256, 256>>>(dst);
    scan_local_kernel<<<scan_blocks, 1024>>>();
    scan_bsum_kernel<<<1, 128>>>(scan_blocks);
    scan_finalize_kernel<<<scan_blocks, 1024>>>();
    scatter_kernel<<<(EE + 255) / 256, 256>>>(src, dst);

    dim3 ggrid(2, (NN + 127) / 128);
    const int nwb = NN / 8;  // 12500 blocks of 8 warps

    // layer 1
    gemm_kernel<<<ggrid, 256>>>(feats_node, 0, W1, 64);
    elr_kernel<<<nwb, 256>>>(al1, ar1);
    aggregate_kernel<<<nwb, 256>>>(bg1);
    // layer 2
    gemm_kernel<<<ggrid, 256>>>(nullptr, 1, W2, 256);
    elr_kernel<<<nwb, 256>>>(al2, ar2);
    aggregate_kernel<<<nwb, 256>>>(bg2);
    // layer 3
    gemm_kernel<<<ggrid, 256>>>(nullptr, 1, W3, 256);
    elr_kernel<<<nwb, 256>>>(al3, ar3);
    aggregate_kernel<<<nwb, 256>>>(bg3);

    // readout + MLP
    score_kernel<<<nwb, 256>>>(sw, sb);
    boundary_kernel<<<(NN + 255) / 256, 256>>>(ng);
    readout_kernel<<<BB, 256>>>(feats_graph);
    mlp_kernel<<<BB, 128>>>(lw1, lb1, lw2, lb2, lw3, lb3, out);
}

// round 16
// speedup vs baseline: 1.1095x; 1.0013x over previous
#include <cuda_runtime.h>

#define NN 100000
#define EE 1600000
#define BB 512
#define HH 4
#define DD 64
#define HD 256
#define EXTRA 16
#define YW (HD + EXTRA)   // 272
#define KC 16             // GEMM K-chunk

// ---------------- scratch (no allocations allowed) ----------------
__device__ __align__(16) float g_h[(size_t)NN * HD];   // GEMM output h
__device__ __align__(16) float g_x[(size_t)NN * HD];   // layer activations
__device__ __align__(16) float g_el[NN * HH];
__device__ __align__(16) float g_er[NN * HH];
__device__ int   g_deg[NN];
__device__ int   g_rowstart[NN + 1];
__device__ int   g_cursor[NN];
__device__ int   g_col[EE];          // src node per CSR slot (grouped by dst)
__device__ float g_w[NN];            // readout scores
__device__ int   g_gstart[BB + 1];
__device__ __align__(16) float g_y[BB * YW];
__device__ int   g_bsum[128];
__device__ int   g_boff[128];

__device__ __forceinline__ float seluf(float v) {
    const float a = 1.6732632423543772f, s = 1.0507009873554805f;
    return v > 0.f ? s * v : s * a * (expf(v) - 1.f);
}
__device__ __forceinline__ float lrelu(float v) { return v > 0.f ? v : 0.2f * v; }

// packed fp32x2 helpers (Blackwell FFMA2 path — only reachable via PTX)
__device__ __forceinline__ unsigned long long ffma2(unsigned long long a,
                                                    unsigned long long b,
                                                    unsigned long long c) {
    unsigned long long d;
    asm("fma.rn.f32x2 %0, %1, %2, %3;" : "=l"(d) : "l"(a), "l"(b), "l"(c));
    return d;
}
__device__ __forceinline__ unsigned long long pack2(float lo, float hi) {
    unsigned long long v;
    asm("mov.b64 %0, {%1, %2};" : "=l"(v) : "f"(lo), "f"(hi));
    return v;
}
__device__ __forceinline__ void unpack2(unsigned long long v, float& lo, float& hi) {
    asm("mov.b64 {%0, %1}, %2;" : "=f"(lo), "=f"(hi) : "l"(v));
}

// ---------------- CSR build ----------------
__global__ void zero_deg_kernel() {
    int i = blockIdx.x * blockDim.x + threadIdx.x;
    if (i < NN) g_deg[i] = 0;
}
__global__ void hist_kernel(const int* __restrict__ dst) {
    int e = blockIdx.x * blockDim.x + threadIdx.x;
    if (e < EE) atomicAdd(&g_deg[dst[e]], 1);
}
// 3-phase parallel scan of g_deg -> g_rowstart (inclusive at i+1) + g_cursor (exclusive)
__global__ __launch_bounds__(1024) void scan_local_kernel() {
    __shared__ int sm[1024];
    int i = blockIdx.x * 1024 + threadIdx.x;
    int v = (i < NN) ? g_deg[i] : 0;
    sm[threadIdx.x] = v;
    __syncthreads();
    for (int off = 1; off < 1024; off <<= 1) {
        int t = (threadIdx.x >= off) ? sm[threadIdx.x - off] : 0;
        __syncthreads();
        sm[threadIdx.x] += t;
        __syncthreads();
    }
    if (i < NN) g_cursor[i] = sm[threadIdx.x];   // local inclusive
    if (threadIdx.x == 1023) g_bsum[blockIdx.x] = sm[1023];
}
__global__ __launch_bounds__(128) void scan_bsum_kernel(int nblocks) {
    __shared__ int sm[128];
    int v = (threadIdx.x < nblocks) ? g_bsum[threadIdx.x] : 0;
    sm[threadIdx.x] = v;
    __syncthreads();
    for (int off = 1; off < 128; off <<= 1) {
        int t = (threadIdx.x >= off) ? sm[threadIdx.x - off] : 0;
        __syncthreads();
        sm[threadIdx.x] += t;
        __syncthreads();
    }
    g_boff[threadIdx.x] = sm[threadIdx.x] - v;   // exclusive
}
__global__ __launch_bounds__(1024) void scan_finalize_kernel() {
    int i = blockIdx.x * 1024 + threadIdx.x;
    if (i >= NN) return;
    int inc = g_cursor[i] + g_boff[blockIdx.x];
    g_rowstart[i + 1] = inc;
    g_cursor[i] = inc - g_deg[i];
    if (i == 0) g_rowstart[0] = 0;
}
__global__ void scatter_kernel(const int* __restrict__ src, const int* __restrict__ dst) {
    int e = blockIdx.x * blockDim.x + threadIdx.x;
    if (e < EE) {
        int pos = atomicAdd(&g_cursor[dst[e]], 1);
        g_col[pos] = src[e];
    }
}

// ---------------- GEMM: C[M,256] = A[M,K] @ B[K,256]  (C = g_h), packed f32x2 ----------------
__global__ __launch_bounds__(256) void gemm_kernel(const float* __restrict__ A_ext,
                                                   int use_gx,
                                                   const float* __restrict__ B,
                                                   int Kdim) {
    const float* __restrict__ A = use_gx ? g_x : A_ext;
    __shared__ float As[KC][128];
    __shared__ float Bs[KC][128];
    int tid = threadIdx.x;
    int bm = blockIdx.y * 128;
    int bn = blockIdx.x * 128;
    int a_row = tid >> 1;            // 0..127
    int a_k   = (tid & 1) << 3;      // 0 or 8
    int b_k   = tid >> 4;            // 0..15
    int b_n   = (tid & 15) << 3;     // 0..120
    int ty = tid >> 4, tx = tid & 15;

    unsigned long long acc2[8][4];
#pragma unroll
    for (int i = 0; i < 8; i++)
#pragma unroll
        for (int j = 0; j < 4; j++) acc2[i][j] = 0ull;

    int gr_a = bm + a_row;
    bool a_ok = gr_a < NN;
    const float* Arow = A + (size_t)gr_a * Kdim;

    for (int k0 = 0; k0 < Kdim; k0 += KC) {
        float4 av0 = make_float4(0.f, 0.f, 0.f, 0.f), av1 = av0;
        if (a_ok) {
            av0 = *(const float4*)(Arow + k0 + a_k);
            av1 = *(const float4*)(Arow + k0 + a_k + 4);
        }
        As[a_k + 0][a_row] = av0.x; As[a_k + 1][a_row] = av0.y;
        As[a_k + 2][a_row] = av0.z; As[a_k + 3][a_row] = av0.w;
        As[a_k + 4][a_row] = av1.x; As[a_k + 5][a_row] = av1.y;
        As[a_k + 6][a_row] = av1.z; As[a_k + 7][a_row] = av1.w;
        const float* Brow = B + (size_t)(k0 + b_k) * 256 + bn + b_n;
        *(float4*)&Bs[b_k][b_n]     = *(const float4*)(Brow);
        *(float4*)&Bs[b_k][b_n + 4] = *(const float4*)(Brow + 4);
        __syncthreads();
#pragma unroll
        for (int k = 0; k < KC; k++) {
            float a_[8];
            *(float4*)&a_[0] = *(const float4*)&As[k][ty * 8];
            *(float4*)&a_[4] = *(const float4*)&As[k][ty * 8 + 4];
            ulonglong2 blo = *(const ulonglong2*)&Bs[k][tx * 8];
            ulonglong2 bhi = *(const ulonglong2*)&Bs[k][tx * 8 + 4];
            unsigned long long b2[4] = {blo.x, blo.y, bhi.x, bhi.y};
#pragma unroll
            for (int i = 0; i < 8; i++) {
                unsigned long long pa = pack2(a_[i], a_[i]);
#pragma unroll
                for (int j = 0; j < 4; j++) acc2[i][j] = ffma2(pa, b2[j], acc2[i][j]);
            }
        }
        __syncthreads();
    }
#pragma unroll
    for (int i = 0; i < 8; i++) {
        int gr = bm + ty * 8 + i;
        if (gr < NN) {
            float c[8];
#pragma unroll
            for (int j = 0; j < 4; j++) unpack2(acc2[i][j], c[2 * j], c[2 * j + 1]);
            float* cp = g_h + (size_t)gr * 256 + bn + tx * 8;
            *(float4*)cp       = make_float4(c[0], c[1], c[2], c[3]);
            *(float4*)(cp + 4) = make_float4(c[4], c[5], c[6], c[7]);
        }
    }
}

// ---------------- per-node attention logits el/er ----------------
__global__ __launch_bounds__(256) void elr_kernel(const float* __restrict__ al,
                                                  const float* __restrict__ ar) {
    int lane = threadIdx.x & 31;
    int v = blockIdx.x * 8 + (threadIdx.x >> 5);
    if (v >= NN) return;
    const float* hrow = g_h + (size_t)v * HD;
    float pl[4] = {0.f, 0.f, 0.f, 0.f}, pr[4] = {0.f, 0.f, 0.f, 0.f};
#pragma unroll
    for (int k = 0; k < 8; k++) {
        int dim = lane + 32 * k;
        float hv = hrow[dim];
        pl[k >> 1] += hv * al[dim];
        pr[k >> 1] += hv * ar[dim];
    }
#pragma unroll
    for (int off = 16; off; off >>= 1) {
#pragma unroll
        for (int h = 0; h < 4; h++) {
            pl[h] += __shfl_xor_sync(0xffffffffu, pl[h], off);
            pr[h] += __shfl_xor_sync(0xffffffffu, pr[h], off);
        }
    }
    if (lane == 0) {
        ((float4*)g_el)[v] = make_float4(pl[0], pl[1], pl[2], pl[3]);
        ((float4*)g_er)[v] = make_float4(pr[0], pr[1], pr[2], pr[3]);
    }
}

// ---------------- segment-softmax + weighted aggregate (one warp per dst node) ----------------
__global__ __launch_bounds__(256) void aggregate_kernel(const float* __restrict__ bias) {
    __shared__ int    s_src[8][32];
    __shared__ float4 s_w[8][32];
    int lane = threadIdx.x & 31;
    int wslot = threadIdx.x >> 5;
    int v = blockIdx.x * 8 + wslot;
    if (v >= NN) return;
    int start = g_rowstart[v], end = g_rowstart[v + 1];
    float4 erv = ((const float4*)g_er)[v];

    // pass 1: per-head max
    float m0 = -1e30f, m1 = -1e30f, m2 = -1e30f, m3 = -1e30f;
    for (int i = start + lane; i < end; i += 32) {
        int s = g_col[i];
        float4 elv = ((const float4*)g_el)[s];
        m0 = fmaxf(m0, lrelu(elv.x + erv.x));
        m1 = fmaxf(m1, lrelu(elv.y + erv.y));
        m2 = fmaxf(m2, lrelu(elv.z + erv.z));
        m3 = fmaxf(m3, lrelu(elv.w + erv.w));
    }
#pragma unroll
    for (int off = 16; off; off >>= 1) {
        m0 = fmaxf(m0, __shfl_xor_sync(0xffffffffu, m0, off));
        m1 = fmaxf(m1, __shfl_xor_sync(0xffffffffu, m1, off));
        m2 = fmaxf(m2, __shfl_xor_sync(0xffffffffu, m2, off));
        m3 = fmaxf(m3, __shfl_xor_sync(0xffffffffu, m3, off));
    }

    // pass 2: exp weights + weighted gather of h[src]
    float acc[8];
#pragma unroll
    for (int k = 0; k < 8; k++) acc[k] = 0.f;
    float den0 = 0.f, den1 = 0.f, den2 = 0.f, den3 = 0.f;

    for (int base = start; base < end; base += 32) {
        int idx = base + lane;
        if (idx < end) {
            int s = g_col[idx];
            float4 elv = ((const float4*)g_el)[s];
            float4 wv;
            wv.x = expf(lrelu(elv.x + erv.x) - m0);
            wv.y = expf(lrelu(elv.y + erv.y) - m1);
            wv.z = expf(lrelu(elv.z + erv.z) - m2);
            wv.w = expf(lrelu(elv.w + erv.w) - m3);
            s_src[wslot][lane] = s;
            s_w[wslot][lane] = wv;
        }
        __syncwarp();
        int cnt = min(32, end - base);
        for (int j = 0; j < cnt; j++) {
            int s = s_src[wslot][j];
            float4 wv = s_w[wslot][j];
            den0 += wv.x; den1 += wv.y; den2 += wv.z; den3 += wv.w;
            const float* hrow = g_h + (size_t)s * HD;
            float warr[4] = {wv.x, wv.y, wv.z, wv.w};
#pragma unroll
            for (int k = 0; k < 8; k++)
                acc[k] += warr[k >> 1] * hrow[lane + 32 * k];
        }
        __syncwarp();
    }
    float den[4] = {den0, den1, den2, den3};
    float* xrow = g_x + (size_t)v * HD;
#pragma unroll
    for (int k = 0; k < 8; k++) {
        int dim = lane + 32 * k;
        float val = acc[k] / fmaxf(den[k >> 1], 1e-9f) + bias[dim];
        xrow[dim] = seluf(val);
    }
}

// ---------------- readout ----------------
__global__ __launch_bounds__(256) void score_kernel(const float* __restrict__ sw,
                                                    const float* __restrict__ sb) {
    int lane = threadIdx.x & 31;
    int v = blockIdx.x * 8 + (threadIdx.x >> 5);
    if (v >= NN) return;
    const float* xr = g_x + (size_t)v * HD;
    float p = 0.f;
#pragma unroll
    for (int k = 0; k < 8; k++) { int dim = lane + 32 * k; p += xr[dim] * sw[dim]; }
#pragma unroll
    for (int off = 16; off; off >>= 1) p += __shfl_xor_sync(0xffffffffu, p, off);
    if (lane == 0) g_w[v] = 1.f / (1.f + expf(-(p + sb[0])));
}

__global__ void boundary_kernel(const int* __restrict__ ng) {
    int i = blockIdx.x * blockDim.x + threadIdx.x;
    if (i >= NN) return;
    int g = ng[i];
    int pg = (i == 0) ? -1 : ng[i - 1];
    for (int gg = pg + 1; gg <= g; gg++) g_gstart[gg] = i;
    if (i == NN - 1)
        for (int gg = g + 1; gg <= BB; gg++) g_gstart[gg] = NN;
}

__global__ __launch_bounds__(256) void readout_kernel(const float* __restrict__ fg) {
    int g = blockIdx.x, d = threadIdx.x;
    int s = g_gstart[g], e = g_gstart[g + 1];
    float num = 0.f, ws = 0.f;
    for (int i = s; i < e; i++) {
        float wv = g_w[i];
        num += wv * g_x[(size_t)i * HD + d];
        ws += wv;
    }
    g_y[g * YW + d] = num / fmaxf(ws, 1e-9f);
    if (d < EXTRA) g_y[g * YW + HD + d] = fg[g * EXTRA + d];
}

// ---------------- MLP head ----------------
__global__ __launch_bounds__(128) void mlp_kernel(const float* __restrict__ lw1,
                                                  const float* __restrict__ lb1,
                                                  const float* __restrict__ lw2,
                                                  const float* __restrict__ lb2,
                                                  const float* __restrict__ lw3,
                                                  const float* __restrict__ lb3,
                                                  float* __restrict__ out) {
    __shared__ float yrow[YW];
    __shared__ float h1[128];
    __shared__ float h2[64];
    int g = blockIdx.x, t = threadIdx.x;
    const float* y = g_y + g * YW;
    yrow[t] = y[t];
    yrow[t + 128] = y[t + 128];
    if (t < 16) yrow[t + 256] = y[t + 256];
    __syncthreads();
    float s = lb1[t];
#pragma unroll 8
    for (int j = 0; j < YW; j++) s += yrow[j] * lw1[j * 128 + t];
    h1[t] = seluf(s);
    __syncthreads();
    if (t < 64) {
        float s2 = lb2[t];
#pragma unroll 8
        for (int j = 0; j < 128; j++) s2 += h1[j] * lw2[j * 64 + t];
        h2[t] = seluf(s2);
    }
    __syncthreads();
    if (t < 32) {
        float p = h2[t] * lw3[t] + h2[t + 32] * lw3[t + 32];
#pragma unroll
        for (int off = 16; off; off >>= 1) p += __shfl_xor_sync(0xffffffffu, p, off);
        if (t == 0) out[g] = p + lb3[0];
    }
}

// ---------------- launch ----------------
extern "C" void kernel_launch(void* const* d_in, const int* in_sizes, int n_in,
                              void* d_out, int out_size) {
    const int*   src = (const int*)d_in[0];
    const int*   dst = (const int*)d_in[1];
    const int*   ng  = (const int*)d_in[2];
    const float* feats_node  = (const float*)d_in[3];
    const float* feats_graph = (const float*)d_in[4];
    const float* W1  = (const float*)d_in[5];
    const float* al1 = (const float*)d_in[6];
    const float* ar1 = (const float*)d_in[7];
    const float* bg1 = (const float*)d_in[8];
    const float* W2  = (const float*)d_in[9];
    const float* al2 = (const float*)d_in[10];
    const float* ar2 = (const float*)d_in[11];
    const float* bg2 = (const float*)d_in[12];
    const float* W3  = (const float*)d_in[13];
    const float* al3 = (const float*)d_in[14];
    const float* ar3 = (const float*)d_in[15];
    const float* bg3 = (const float*)d_in[16];
    const float* sw  = (const float*)d_in[17];
    const float* sb  = (const float*)d_in[18];
    const float* lw1 = (const float*)d_in[19];
    const float* lb1 = (const float*)d_in[20];
    const float* lw2 = (const float*)d_in[21];
    const float* lb2 = (const float*)d_in[22];
    const float* lw3 = (const float*)d_in[23];
    const float* lb3 = (const float*)d_in[24];
    float* out = (float*)d_out;

    const int scan_blocks = (NN + 1023) / 1024;  // 98

    // CSR by dst (rebuilt every call: no caching allowed)
    zero_deg_kernel<<<(NN + 255) / 256, 256>>>();
    hist_kernel<<<(EE + 255) / 256, 256>>>(dst);
    scan_local_kernel<<<scan_blocks, 1024>>>();
    scan_bsum_kernel<<<1, 128>>>(scan_blocks);
    scan_finalize_kernel<<<scan_blocks, 1024>>>();
    scatter_kernel<<<(EE + 255) / 256, 256>>>(src, dst);

    dim3 ggrid(2, (NN + 127) / 128);
    const int nwb = NN / 8;  // 12500 blocks of 8 warps

    // layer 1
    gemm_kernel<<<ggrid, 256>>>(feats_node, 0, W1, 64);
    elr_kernel<<<nwb, 256>>>(al1, ar1);
    aggregate_kernel<<<nwb, 256>>>(bg1);
    // layer 2
    gemm_kernel<<<ggrid, 256>>>(nullptr, 1, W2, 256);
    elr_kernel<<<nwb, 256>>>(al2, ar2);
    aggregate_kernel<<<nwb, 256>>>(bg2);
    // layer 3
    gemm_kernel<<<ggrid, 256>>>(nullptr, 1, W3, 256);
    elr_kernel<<<nwb, 256>>>(al3, ar3);
    aggregate_kernel<<<nwb, 256>>>(bg3);

    // readout + MLP
    score_kernel<<<nwb, 256>>>(sw, sb);
    boundary_kernel<<<(NN + 255) / 256, 256>>>(ng);
    readout_kernel<<<BB, 256>>>(feats_graph);
    mlp_kernel<<<BB, 128>>>(lw1, lb1, lw2, lb2, lw3, lb3, out);
}